// round 1
// baseline (speedup 1.0000x reference)
#include <cuda_runtime.h>
#include <cuda_bf16.h>

#define NMAX 100000
#define EMAX 1600000
#define HF   64          // HEADS * OUT_FEATS
#define HEADS 4
#define INF  128

// Scratch (allocation-free rule: __device__ globals)
__device__ float g_h[(size_t)NMAX * HF];        // 25.6 MB
__device__ float g_el[(size_t)NMAX * HEADS];
__device__ float g_er[(size_t)NMAX * HEADS];
__device__ float g_ev[(size_t)EMAX * HEADS];    // 25.6 MB
__device__ float g_denom[(size_t)NMAX * HEADS];

// ---------------------------------------------------------------------------
// Zero output + denom (d_out is poisoned 0xAA by the harness)
// ---------------------------------------------------------------------------
__global__ void zero_kernel(float* __restrict__ out, int n_nodes) {
    int i = blockIdx.x * blockDim.x + threadIdx.x;
    if (i < n_nodes * HF)    out[i] = 0.0f;
    if (i < n_nodes * HEADS) g_denom[i] = 0.0f;
}

// ---------------------------------------------------------------------------
// Fused: h = feat @ W  (N x 128 @ 128 x 64), plus el/er head reductions.
// Block: 256 threads handles 32 nodes. W (32KB) + feat tile (16KB) in smem.
// Register blocking: each thread computes 2 nodes x 4 cols (cols cg+16j).
// ---------------------------------------------------------------------------
__global__ __launch_bounds__(256) void gemm_el_er_kernel(
    const float* __restrict__ feat,
    const float* __restrict__ W,
    const float* __restrict__ attn_l,
    const float* __restrict__ attn_r,
    int n_nodes)
{
    __shared__ float Ws[INF * HF];   // 32 KB, W[k][c] row-major
    __shared__ float Fs[32 * INF];   // 16 KB; later reused as Hs[32][65]

    const int tid  = threadIdx.x;
    const int base = blockIdx.x * 32;

    // Load W (coalesced float4)
    #pragma unroll
    for (int i = tid; i < INF * HF / 4; i += 256)
        ((float4*)Ws)[i] = ((const float4*)W)[i];

    // Load 32-node feat tile (zero-pad past N)
    for (int i4 = tid; i4 < 32 * INF / 4; i4 += 256) {
        int node = base + (i4 >> 5);            // 32 float4 per row
        float4 v = make_float4(0.f, 0.f, 0.f, 0.f);
        if (node < n_nodes)
            v = ((const float4*)feat)[(size_t)node * (INF / 4) + (i4 & 31)];
        ((float4*)Fs)[i4] = v;
    }
    __syncthreads();

    const int cg = tid & 15;   // column group: cols cg, cg+16, cg+32, cg+48
    const int np = tid >> 4;   // node pair: nodes 2*np, 2*np+1
    const float* f0 = &Fs[(2 * np) * INF];
    const float* f1 = f0 + INF;

    float a00 = 0.f, a01 = 0.f, a02 = 0.f, a03 = 0.f;
    float a10 = 0.f, a11 = 0.f, a12 = 0.f, a13 = 0.f;

    #pragma unroll 8
    for (int k = 0; k < INF; k++) {
        float fa = f0[k];
        float fb = f1[k];
        const float* wr = &Ws[k * HF + cg];
        float w0 = wr[0], w1 = wr[16], w2 = wr[32], w3 = wr[48];
        a00 += fa * w0; a01 += fa * w1; a02 += fa * w2; a03 += fa * w3;
        a10 += fb * w0; a11 += fb * w1; a12 += fb * w2; a13 += fb * w3;
    }

    __syncthreads();   // done reading Fs; reuse as Hs

    float* Hs = Fs;    // logical [32][65] (stride 65 kills bank conflicts)
    const int r0 = 2 * np, r1 = 2 * np + 1;
    Hs[r0 * 65 + cg     ] = a00;  Hs[r0 * 65 + cg + 16] = a01;
    Hs[r0 * 65 + cg + 32] = a02;  Hs[r0 * 65 + cg + 48] = a03;
    Hs[r1 * 65 + cg     ] = a10;  Hs[r1 * 65 + cg + 16] = a11;
    Hs[r1 * 65 + cg + 32] = a12;  Hs[r1 * 65 + cg + 48] = a13;

    const int n0 = base + r0, n1 = base + r1;
    if (n0 < n_nodes) {
        float* hp = &g_h[(size_t)n0 * HF];
        hp[cg] = a00; hp[cg + 16] = a01; hp[cg + 32] = a02; hp[cg + 48] = a03;
    }
    if (n1 < n_nodes) {
        float* hp = &g_h[(size_t)n1 * HF];
        hp[cg] = a10; hp[cg + 16] = a11; hp[cg + 32] = a12; hp[cg + 48] = a13;
    }
    __syncthreads();

    // el/er: thread t (t<32) handles node base+t. attn_* are 64 floats (L1 bcast).
    if (tid < 32) {
        int n = base + tid;
        if (n < n_nodes) {
            #pragma unroll
            for (int head = 0; head < HEADS; head++) {
                float sl = 0.f, sr = 0.f;
                #pragma unroll
                for (int f = 0; f < 16; f++) {
                    float v = Hs[tid * 65 + head * 16 + f];
                    sl += v * attn_l[head * 16 + f];
                    sr += v * attn_r[head * 16 + f];
                }
                g_el[(size_t)n * HEADS + head] = sl;
                g_er[(size_t)n * HEADS + head] = sr;
            }
        }
    }
}

// ---------------------------------------------------------------------------
// Edge scores: s = LeakyReLU(el[src]+er[trg]); e = exp(s) (global-max shift
// cancels exactly in attn = e/denom, so it is skipped); accumulate denom.
// ---------------------------------------------------------------------------
__device__ __forceinline__ float lrelu_exp(float x) {
    x = (x > 0.f) ? x : 0.2f * x;
    return __expf(x);
}

__global__ __launch_bounds__(256) void score_kernel(
    const int* __restrict__ src, const int* __restrict__ trg, int n_edges)
{
    int e = blockIdx.x * 256 + threadIdx.x;
    if (e >= n_edges) return;
    int s = src[e], t = trg[e];
    float4 a = *(const float4*)&g_el[(size_t)s * HEADS];
    float4 b = *(const float4*)&g_er[(size_t)t * HEADS];
    float4 v;
    v.x = lrelu_exp(a.x + b.x);
    v.y = lrelu_exp(a.y + b.y);
    v.z = lrelu_exp(a.z + b.z);
    v.w = lrelu_exp(a.w + b.w);
    *(float4*)&g_ev[(size_t)e * HEADS] = v;
    asm volatile("red.global.add.v4.f32 [%0], {%1,%2,%3,%4};"
                 :: "l"(&g_denom[(size_t)t * HEADS]),
                    "f"(v.x), "f"(v.y), "f"(v.z), "f"(v.w) : "memory");
}

// ---------------------------------------------------------------------------
// Aggregation: out[trg] += h[src] * (ev / (denom[trg]+eps)).
// 16 threads per edge, each owns one float4 (16B) of the 64-float message.
// Vectorized L2 reductions (red.global.add.v4.f32) cut lane-requests 4x.
// ---------------------------------------------------------------------------
__global__ __launch_bounds__(256) void agg_kernel(
    const int* __restrict__ src, const int* __restrict__ trg,
    float* __restrict__ out, int n_edges)
{
    int idx = blockIdx.x * 256 + threadIdx.x;
    int e = idx >> 4;
    if (e >= n_edges) return;
    int l = idx & 15;                 // float4 slot 0..15 -> cols 4l..4l+3
    int s = src[e], t = trg[e];
    int head = l >> 2;                // cols 4l..4l+3 all within head l/4
    float ev = g_ev[(size_t)e * HEADS + head];
    float dn = g_denom[(size_t)t * HEADS + head];
    float a = ev / (dn + 1e-16f);
    float4 hv = *(const float4*)&g_h[(size_t)s * HF + l * 4];
    hv.x *= a; hv.y *= a; hv.z *= a; hv.w *= a;
    asm volatile("red.global.add.v4.f32 [%0], {%1,%2,%3,%4};"
                 :: "l"(&out[(size_t)t * HF + l * 4]),
                    "f"(hv.x), "f"(hv.y), "f"(hv.z), "f"(hv.w) : "memory");
}

// ---------------------------------------------------------------------------
// Launch: zero -> gemm+el/er -> scores+denom -> aggregate. All graph-capturable.
// ---------------------------------------------------------------------------
extern "C" void kernel_launch(void* const* d_in, const int* in_sizes, int n_in,
                              void* d_out, int out_size)
{
    const float* feat   = (const float*)d_in[0];   // [N,128]
    const float* W      = (const float*)d_in[1];   // [128,64]
    const float* attn_l = (const float*)d_in[2];   // [1,4,16]
    const float* attn_r = (const float*)d_in[3];   // [1,4,16]
    const int*   src    = (const int*)d_in[4];     // [E]
    const int*   trg    = (const int*)d_in[5];     // [E]
    float* out = (float*)d_out;                    // [N,64]

    int n_nodes = in_sizes[0] / INF;
    int n_edges = in_sizes[4];

    zero_kernel<<<(n_nodes * HF + 255) / 256, 256>>>(out, n_nodes);
    gemm_el_er_kernel<<<(n_nodes + 31) / 32, 256>>>(feat, W, attn_l, attn_r, n_nodes);
    score_kernel<<<(n_edges + 255) / 256, 256>>>(src, trg, n_edges);
    agg_kernel<<<((long long)n_edges * 16 + 255) / 256, 256>>>(src, trg, out, n_edges);
}

// round 2
// speedup vs baseline: 1.3215x; 1.3215x over previous
#include <cuda_runtime.h>
#include <cuda_bf16.h>

#define NMAX  100000
#define EMAX  1600000
#define HF    64          // HEADS * OUT_FEATS
#define HEADS 4
#define INF   128
#define SCAN_B 1024       // elements per scan block
#define NBLK  ((NMAX + SCAN_B - 1) / SCAN_B)   // 98

// ------------------------- device scratch (no allocs) -----------------------
__device__ float g_h[(size_t)NMAX * HF];        // 25.6 MB
__device__ float g_el[(size_t)NMAX * HEADS];
__device__ float g_er[(size_t)NMAX * HEADS];
__device__ int   g_cnt[NMAX];                   // in-degree per node
__device__ int   g_excl[NMAX];                  // within-block exclusive scan
__device__ int   g_base[NMAX];                  // global CSR row start
__device__ int   g_cur[NMAX];                   // scatter cursors
__device__ int   g_bsum[NBLK];                  // per-block totals
__device__ int   g_boff[NBLK];                  // scanned block offsets
__device__ int   g_esrc[EMAX];                  // src node, grouped by target
__device__ float g_ev4[(size_t)EMAX * HEADS];   // exp-scores, grouped by target

// ---------------------------------------------------------------------------
// 0. zero the counters/cursors (out needs no zeroing: agg writes every slot)
// ---------------------------------------------------------------------------
__global__ void zero_kernel(int n_nodes) {
    int i = blockIdx.x * blockDim.x + threadIdx.x;
    if (i < n_nodes) { g_cnt[i] = 0; g_cur[i] = 0; }
}

// ---------------------------------------------------------------------------
// 1. fused GEMM h = feat @ W  (Nx128 @ 128x64) + el/er head reductions
// ---------------------------------------------------------------------------
__global__ __launch_bounds__(256) void gemm_el_er_kernel(
    const float* __restrict__ feat, const float* __restrict__ W,
    const float* __restrict__ attn_l, const float* __restrict__ attn_r,
    int n_nodes)
{
    __shared__ float Ws[INF * HF];   // 32 KB
    __shared__ float Fs[32 * INF];   // 16 KB, reused as Hs[32][65]

    const int tid  = threadIdx.x;
    const int base = blockIdx.x * 32;

    #pragma unroll
    for (int i = tid; i < INF * HF / 4; i += 256)
        ((float4*)Ws)[i] = ((const float4*)W)[i];

    for (int i4 = tid; i4 < 32 * INF / 4; i4 += 256) {
        int node = base + (i4 >> 5);
        float4 v = make_float4(0.f, 0.f, 0.f, 0.f);
        if (node < n_nodes)
            v = ((const float4*)feat)[(size_t)node * (INF / 4) + (i4 & 31)];
        ((float4*)Fs)[i4] = v;
    }
    __syncthreads();

    const int cg = tid & 15;
    const int np = tid >> 4;
    const float* f0 = &Fs[(2 * np) * INF];
    const float* f1 = f0 + INF;

    float a00=0.f,a01=0.f,a02=0.f,a03=0.f,a10=0.f,a11=0.f,a12=0.f,a13=0.f;
    #pragma unroll 8
    for (int k = 0; k < INF; k++) {
        float fa = f0[k], fb = f1[k];
        const float* wr = &Ws[k * HF + cg];
        float w0 = wr[0], w1 = wr[16], w2 = wr[32], w3 = wr[48];
        a00 += fa*w0; a01 += fa*w1; a02 += fa*w2; a03 += fa*w3;
        a10 += fb*w0; a11 += fb*w1; a12 += fb*w2; a13 += fb*w3;
    }
    __syncthreads();

    float* Hs = Fs;  // [32][65]
    const int r0 = 2*np, r1 = 2*np+1;
    Hs[r0*65+cg]=a00; Hs[r0*65+cg+16]=a01; Hs[r0*65+cg+32]=a02; Hs[r0*65+cg+48]=a03;
    Hs[r1*65+cg]=a10; Hs[r1*65+cg+16]=a11; Hs[r1*65+cg+32]=a12; Hs[r1*65+cg+48]=a13;

    const int n0 = base + r0, n1 = base + r1;
    if (n0 < n_nodes) {
        float* hp = &g_h[(size_t)n0 * HF];
        hp[cg]=a00; hp[cg+16]=a01; hp[cg+32]=a02; hp[cg+48]=a03;
    }
    if (n1 < n_nodes) {
        float* hp = &g_h[(size_t)n1 * HF];
        hp[cg]=a10; hp[cg+16]=a11; hp[cg+32]=a12; hp[cg+48]=a13;
    }
    __syncthreads();

    if (tid < 32) {
        int n = base + tid;
        if (n < n_nodes) {
            #pragma unroll
            for (int head = 0; head < HEADS; head++) {
                float sl = 0.f, sr = 0.f;
                #pragma unroll
                for (int f = 0; f < 16; f++) {
                    float v = Hs[tid*65 + head*16 + f];
                    sl += v * attn_l[head*16 + f];
                    sr += v * attn_r[head*16 + f];
                }
                g_el[(size_t)n * HEADS + head] = sl;
                g_er[(size_t)n * HEADS + head] = sr;
            }
        }
    }
}

// ---------------------------------------------------------------------------
// 2. in-degree histogram
// ---------------------------------------------------------------------------
__global__ void hist_kernel(const int* __restrict__ trg, int n_edges) {
    int e = blockIdx.x * blockDim.x + threadIdx.x;
    if (e < n_edges) atomicAdd(&g_cnt[trg[e]], 1);
}

// ---------------------------------------------------------------------------
// 3a/3b/3c. exclusive scan of g_cnt -> g_base
// ---------------------------------------------------------------------------
__global__ __launch_bounds__(SCAN_B) void scan1_kernel(int n_nodes) {
    __shared__ int s[SCAN_B];
    int i = blockIdx.x * SCAN_B + threadIdx.x;
    int v = (i < n_nodes) ? g_cnt[i] : 0;
    s[threadIdx.x] = v;
    __syncthreads();
    #pragma unroll
    for (int off = 1; off < SCAN_B; off <<= 1) {
        int add = (threadIdx.x >= off) ? s[threadIdx.x - off] : 0;
        __syncthreads();
        s[threadIdx.x] += add;
        __syncthreads();
    }
    if (i < n_nodes) g_excl[i] = s[threadIdx.x] - v;
    if (threadIdx.x == SCAN_B - 1) g_bsum[blockIdx.x] = s[SCAN_B - 1];
}

__global__ __launch_bounds__(128) void scan2_kernel(int n_blocks) {
    __shared__ int s[128];
    int v = (threadIdx.x < n_blocks) ? g_bsum[threadIdx.x] : 0;
    s[threadIdx.x] = v;
    __syncthreads();
    #pragma unroll
    for (int off = 1; off < 128; off <<= 1) {
        int add = (threadIdx.x >= off) ? s[threadIdx.x - off] : 0;
        __syncthreads();
        s[threadIdx.x] += add;
        __syncthreads();
    }
    if (threadIdx.x < n_blocks) g_boff[threadIdx.x] = s[threadIdx.x] - v;
}

__global__ void scan3_kernel(int n_nodes) {
    int i = blockIdx.x * blockDim.x + threadIdx.x;
    if (i < n_nodes) g_base[i] = g_excl[i] + g_boff[i >> 10];
}

// ---------------------------------------------------------------------------
// 4. scatter edges into target-grouped order, fusing score computation.
//    (global-max shift in the reference cancels exactly in ev/denom; skipped)
// ---------------------------------------------------------------------------
__device__ __forceinline__ float lrelu_exp(float x) {
    x = (x > 0.f) ? x : 0.2f * x;
    return __expf(x);
}

__global__ __launch_bounds__(256) void scatter_kernel(
    const int* __restrict__ src, const int* __restrict__ trg, int n_edges)
{
    int e = blockIdx.x * 256 + threadIdx.x;
    if (e >= n_edges) return;
    int s = src[e], t = trg[e];
    float4 a = *(const float4*)&g_el[(size_t)s * HEADS];
    float4 b = *(const float4*)&g_er[(size_t)t * HEADS];
    float4 v;
    v.x = lrelu_exp(a.x + b.x);
    v.y = lrelu_exp(a.y + b.y);
    v.z = lrelu_exp(a.z + b.z);
    v.w = lrelu_exp(a.w + b.w);
    int pos = g_base[t] + atomicAdd(&g_cur[t], 1);
    g_esrc[pos] = s;
    *(float4*)&g_ev4[(size_t)pos * HEADS] = v;
}

// ---------------------------------------------------------------------------
// 5. CSR aggregation: 16 threads per node, each owns one float4 column slot.
//    Single pass: acc += ev * h[src], dsum += ev; out = acc / (dsum + eps).
//    No atomics, coalesced stores, full overwrite of out.
// ---------------------------------------------------------------------------
__global__ __launch_bounds__(256) void agg_csr_kernel(
    float* __restrict__ out, int n_nodes)
{
    int idx = blockIdx.x * 256 + threadIdx.x;
    int n = idx >> 4;
    if (n >= n_nodes) return;
    int l = idx & 15;        // float4 slot -> cols 4l..4l+3
    int head = l >> 2;

    int beg = g_base[n];
    int end = beg + g_cnt[n];

    float4 acc = make_float4(0.f, 0.f, 0.f, 0.f);
    float dsum = 0.f;

    for (int p = beg; p < end; p++) {
        int   s  = g_esrc[p];                         // broadcast in half-warp
        float ev = g_ev4[(size_t)p * HEADS + head];
        float4 hv = *(const float4*)&g_h[(size_t)s * HF + l * 4];
        acc.x += ev * hv.x; acc.y += ev * hv.y;
        acc.z += ev * hv.z; acc.w += ev * hv.w;
        dsum  += ev;
    }
    float inv = 1.0f / (dsum + 1e-16f);
    acc.x *= inv; acc.y *= inv; acc.z *= inv; acc.w *= inv;
    *(float4*)&out[(size_t)n * HF + l * 4] = acc;
}

// ---------------------------------------------------------------------------
extern "C" void kernel_launch(void* const* d_in, const int* in_sizes, int n_in,
                              void* d_out, int out_size)
{
    const float* feat   = (const float*)d_in[0];
    const float* W      = (const float*)d_in[1];
    const float* attn_l = (const float*)d_in[2];
    const float* attn_r = (const float*)d_in[3];
    const int*   src    = (const int*)d_in[4];
    const int*   trg    = (const int*)d_in[5];
    float* out = (float*)d_out;

    int n_nodes  = in_sizes[0] / INF;
    int n_edges  = in_sizes[4];
    int n_sblk   = (n_nodes + SCAN_B - 1) / SCAN_B;

    zero_kernel<<<(n_nodes + 255) / 256, 256>>>(n_nodes);
    gemm_el_er_kernel<<<(n_nodes + 31) / 32, 256>>>(feat, W, attn_l, attn_r, n_nodes);
    hist_kernel<<<(n_edges + 255) / 256, 256>>>(trg, n_edges);
    scan1_kernel<<<n_sblk, SCAN_B>>>(n_nodes);
    scan2_kernel<<<1, 128>>>(n_sblk);
    scan3_kernel<<<(n_nodes + 255) / 256, 256>>>(n_nodes);
    scatter_kernel<<<(n_edges + 255) / 256, 256>>>(src, trg, n_edges);
    agg_csr_kernel<<<((long long)n_nodes * 16 + 255) / 256, 256>>>(out, n_nodes);
}

// round 8
// speedup vs baseline: 1.5143x; 1.1459x over previous
#include <cuda_runtime.h>
#include <cuda_bf16.h>

#define NMAX  100000
#define EMAX  1600000
#define HF    64          // HEADS * OUT_FEATS
#define HEADS 4
#define INF   128
#define SCAN_B 1024
#define NBLK  ((NMAX + SCAN_B - 1) / SCAN_B)   // 98

typedef unsigned long long ull;

// ------------------------- device scratch (no allocs) -----------------------
__device__ float g_h[(size_t)NMAX * HF];        // 25.6 MB
__device__ float g_el[(size_t)NMAX * HEADS];
__device__ float g_er[(size_t)NMAX * HEADS];
__device__ int   g_cnt[NMAX];
__device__ int   g_excl[NMAX];
__device__ int   g_base[NMAX];
__device__ int   g_cur[NMAX];
__device__ int   g_bsum[NBLK];
__device__ int   g_boff[NBLK];
__device__ int   g_esrc[EMAX];                  // src node, grouped by target

// ------------------------- f32x2 helpers ------------------------------------
__device__ __forceinline__ void ffma2(ull& d, ull a, ull b) {
    asm("fma.rn.f32x2 %0, %1, %2, %3;" : "=l"(d) : "l"(a), "l"(b), "l"(d));
}
__device__ __forceinline__ ull pack2(float x, float y) {
    ull r; asm("mov.b64 %0, {%1, %2};" : "=l"(r) : "f"(x), "f"(y)); return r;
}
union F4U2 { float4 f4; ull u[2]; };
union U1F2 { ull u; float2 f; };

// ---------------------------------------------------------------------------
// 0. zero in-degree counters
// ---------------------------------------------------------------------------
__global__ void zero_kernel(int n_nodes) {
    int i = blockIdx.x * blockDim.x + threadIdx.x;
    if (i < n_nodes) g_cnt[i] = 0;
}

// ---------------------------------------------------------------------------
// 1. fused GEMM h = feat @ W (Nx128 @ 128x64) via packed f32x2 FMA,
//    + el/er head reductions via register partials + shfl butterfly.
//    256 threads / 32 nodes per block. Thread owns 2 nodes x 4 consecutive cols.
// ---------------------------------------------------------------------------
__global__ __launch_bounds__(256) void gemm_el_er_kernel(
    const float* __restrict__ feat, const float* __restrict__ W,
    const float* __restrict__ attn_l, const float* __restrict__ attn_r,
    int n_nodes)
{
    __shared__ float Ws[INF * HF];   // 32 KB
    __shared__ float Fs[32 * INF];   // 16 KB

    const int tid  = threadIdx.x;
    const int base = blockIdx.x * 32;

    #pragma unroll
    for (int i = tid; i < INF * HF / 4; i += 256)
        ((float4*)Ws)[i] = ((const float4*)W)[i];

    for (int i4 = tid; i4 < 32 * INF / 4; i4 += 256) {
        int node = base + (i4 >> 5);
        float4 v = make_float4(0.f, 0.f, 0.f, 0.f);
        if (node < n_nodes)
            v = ((const float4*)feat)[(size_t)node * (INF / 4) + (i4 & 31)];
        ((float4*)Fs)[i4] = v;
    }
    __syncthreads();

    const int cq = tid & 15;          // column quad: cols 4cq .. 4cq+3
    const int np = tid >> 4;          // node pair: nodes 2np, 2np+1
    const float* f0 = &Fs[(2 * np) * INF];
    const float* f1 = f0 + INF;

    ull A0 = 0, A1 = 0, B0 = 0, B1 = 0;   // packed fp32 pairs, 0ull == (0.f,0.f)

    #pragma unroll 8
    for (int k = 0; k < INF; k += 2) {
        float2 fA = *(const float2*)&f0[k];
        float2 fB = *(const float2*)&f1[k];
        F4U2 w0; w0.f4 = *(const float4*)&Ws[k * HF + 4 * cq];
        F4U2 w1; w1.f4 = *(const float4*)&Ws[(k + 1) * HF + 4 * cq];
        ull fa0 = pack2(fA.x, fA.x), fa1 = pack2(fA.y, fA.y);
        ull fb0 = pack2(fB.x, fB.x), fb1 = pack2(fB.y, fB.y);
        ffma2(A0, fa0, w0.u[0]); ffma2(A1, fa0, w0.u[1]);
        ffma2(B0, fb0, w0.u[0]); ffma2(B1, fb0, w0.u[1]);
        ffma2(A0, fa1, w1.u[0]); ffma2(A1, fa1, w1.u[1]);
        ffma2(B0, fb1, w1.u[0]); ffma2(B1, fb1, w1.u[1]);
    }

    U1F2 a0; a0.u = A0;  U1F2 a1; a1.u = A1;   // node0 cols 4cq..4cq+3
    U1F2 b0; b0.u = B0;  U1F2 b1; b1.u = B1;   // node1

    const int n0 = base + 2 * np, n1 = n0 + 1;
    if (n0 < n_nodes)
        *(float4*)&g_h[(size_t)n0 * HF + 4 * cq] =
            make_float4(a0.f.x, a0.f.y, a1.f.x, a1.f.y);
    if (n1 < n_nodes)
        *(float4*)&g_h[(size_t)n1 * HF + 4 * cq] =
            make_float4(b0.f.x, b0.f.y, b1.f.x, b1.f.y);

    // el/er: cols 4cq..4cq+3 lie inside head (cq>>2). Partial dot per thread,
    // butterfly-reduce over the 4 threads (cq&3) sharing a head.
    float al0 = attn_l[4*cq], al1 = attn_l[4*cq+1], al2 = attn_l[4*cq+2], al3 = attn_l[4*cq+3];
    float ar0 = attn_r[4*cq], ar1 = attn_r[4*cq+1], ar2 = attn_r[4*cq+2], ar3 = attn_r[4*cq+3];

    float el0 = a0.f.x*al0 + a0.f.y*al1 + a1.f.x*al2 + a1.f.y*al3;
    float er0 = a0.f.x*ar0 + a0.f.y*ar1 + a1.f.x*ar2 + a1.f.y*ar3;
    float el1 = b0.f.x*al0 + b0.f.y*al1 + b1.f.x*al2 + b1.f.y*al3;
    float er1 = b0.f.x*ar0 + b0.f.y*ar1 + b1.f.x*ar2 + b1.f.y*ar3;

    #pragma unroll
    for (int off = 1; off <= 2; off <<= 1) {
        el0 += __shfl_xor_sync(0xffffffffu, el0, off);
        er0 += __shfl_xor_sync(0xffffffffu, er0, off);
        el1 += __shfl_xor_sync(0xffffffffu, el1, off);
        er1 += __shfl_xor_sync(0xffffffffu, er1, off);
    }
    if ((cq & 3) == 0) {
        int head = cq >> 2;
        if (n0 < n_nodes) {
            g_el[(size_t)n0 * HEADS + head] = el0;
            g_er[(size_t)n0 * HEADS + head] = er0;
        }
        if (n1 < n_nodes) {
            g_el[(size_t)n1 * HEADS + head] = el1;
            g_er[(size_t)n1 * HEADS + head] = er1;
        }
    }
}

// ---------------------------------------------------------------------------
// 2. in-degree histogram
// ---------------------------------------------------------------------------
__global__ void hist_kernel(const int* __restrict__ trg, int n_edges) {
    int e = blockIdx.x * blockDim.x + threadIdx.x;
    if (e < n_edges) atomicAdd(&g_cnt[trg[e]], 1);
}

// ---------------------------------------------------------------------------
// 3. exclusive scan of g_cnt (warp-shuffle based)
// ---------------------------------------------------------------------------
__global__ __launch_bounds__(SCAN_B) void scan1_kernel(int n_nodes) {
    __shared__ int warpsum[32];
    int i = blockIdx.x * SCAN_B + threadIdx.x;
    int lane = threadIdx.x & 31, wid = threadIdx.x >> 5;
    int v = (i < n_nodes) ? g_cnt[i] : 0;
    int x = v;
    #pragma unroll
    for (int off = 1; off < 32; off <<= 1) {
        int y = __shfl_up_sync(0xffffffffu, x, off);
        if (lane >= off) x += y;
    }
    if (lane == 31) warpsum[wid] = x;
    __syncthreads();
    if (threadIdx.x < 32) {
        int w = warpsum[threadIdx.x];
        int xs = w;
        #pragma unroll
        for (int off = 1; off < 32; off <<= 1) {
            int y = __shfl_up_sync(0xffffffffu, xs, off);
            if (threadIdx.x >= off) xs += y;
        }
        warpsum[threadIdx.x] = xs - w;    // exclusive warp offsets
    }
    __syncthreads();
    int excl = x - v + warpsum[wid];
    if (i < n_nodes) g_excl[i] = excl;
    if (threadIdx.x == SCAN_B - 1) g_bsum[blockIdx.x] = excl + v;
}

__global__ __launch_bounds__(128) void scan2_kernel(int n_blocks) {
    __shared__ int s[128];
    int v = (threadIdx.x < n_blocks) ? g_bsum[threadIdx.x] : 0;
    s[threadIdx.x] = v;
    __syncthreads();
    #pragma unroll
    for (int off = 1; off < 128; off <<= 1) {
        int add = (threadIdx.x >= off) ? s[threadIdx.x - off] : 0;
        __syncthreads();
        s[threadIdx.x] += add;
        __syncthreads();
    }
    if (threadIdx.x < n_blocks) g_boff[threadIdx.x] = s[threadIdx.x] - v;
}

__global__ void scan3_kernel(int n_nodes) {
    int i = blockIdx.x * blockDim.x + threadIdx.x;
    if (i < n_nodes) {
        int b = g_excl[i] + g_boff[i >> 10];
        g_base[i] = b;
        g_cur[i]  = b;    // scatter cursors pre-seeded to row start
    }
}

// ---------------------------------------------------------------------------
// 4. int-only scatter: group src indices by target.
// ---------------------------------------------------------------------------
__global__ __launch_bounds__(256) void scatter_kernel(
    const int* __restrict__ src, const int* __restrict__ trg, int n_edges)
{
    int e = blockIdx.x * 256 + threadIdx.x;
    if (e >= n_edges) return;
    int pos = atomicAdd(&g_cur[trg[e]], 1);
    g_esrc[pos] = src[e];
}

// ---------------------------------------------------------------------------
// 5. CSR aggregation, ev recomputed in-loop (redundant per-lane exp is free at
//    warp granularity; all 16 lanes share s so el load is a line broadcast).
//    (Reference's global-max shift cancels exactly in ev/denom; skipped.)
// ---------------------------------------------------------------------------
__global__ __launch_bounds__(256) void agg_csr_kernel(
    float* __restrict__ out, int n_nodes)
{
    int idx = blockIdx.x * 256 + threadIdx.x;
    int n = idx >> 4;
    if (n >= n_nodes) return;
    int l = idx & 15;          // float4 slot -> cols 4l..4l+3
    int head = l >> 2;

    int beg = g_base[n];
    int end = beg + g_cnt[n];
    float ern = g_er[(size_t)n * HEADS + head];

    float4 acc = make_float4(0.f, 0.f, 0.f, 0.f);
    float dsum = 0.f;

    #pragma unroll 2
    for (int p = beg; p < end; p++) {
        int s = g_esrc[p];
        float x = g_el[(size_t)s * HEADS + head] + ern;
        x = (x > 0.f) ? x : 0.2f * x;
        float ev = __expf(x);
        float4 hv = *(const float4*)&g_h[(size_t)s * HF + l * 4];
        acc.x += ev * hv.x; acc.y += ev * hv.y;
        acc.z += ev * hv.z; acc.w += ev * hv.w;
        dsum  += ev;
    }
    float inv = 1.0f / (dsum + 1e-16f);
    acc.x *= inv; acc.y *= inv; acc.z *= inv; acc.w *= inv;
    *(float4*)&out[(size_t)n * HF + l * 4] = acc;
}

// ---------------------------------------------------------------------------
extern "C" void kernel_launch(void* const* d_in, const int* in_sizes, int n_in,
                              void* d_out, int out_size)
{
    const float* feat   = (const float*)d_in[0];
    const float* W      = (const float*)d_in[1];
    const float* attn_l = (const float*)d_in[2];
    const float* attn_r = (const float*)d_in[3];
    const int*   src    = (const int*)d_in[4];
    const int*   trg    = (const int*)d_in[5];
    float* out = (float*)d_out;

    int n_nodes = in_sizes[0] / INF;
    int n_edges = in_sizes[4];
    int n_sblk  = (n_nodes + SCAN_B - 1) / SCAN_B;

    zero_kernel<<<(n_nodes + 255) / 256, 256>>>(n_nodes);
    gemm_el_er_kernel<<<(n_nodes + 31) / 32, 256>>>(feat, W, attn_l, attn_r, n_nodes);
    hist_kernel<<<(n_edges + 255) / 256, 256>>>(trg, n_edges);
    scan1_kernel<<<n_sblk, SCAN_B>>>(n_nodes);
    scan2_kernel<<<1, 128>>>(n_sblk);
    scan3_kernel<<<(n_nodes + 255) / 256, 256>>>(n_nodes);
    scatter_kernel<<<(n_edges + 255) / 256, 256>>>(src, trg, n_edges);
    agg_csr_kernel<<<((long long)n_nodes * 16 + 255) / 256, 256>>>(out, n_nodes);
}